// round 1
// baseline (speedup 1.0000x reference)
#include <cuda_runtime.h>
#include <math.h>
#include <float.h>

#define BB 8
#define SS 512
#define EE 768
#define HH 12
#define DD 64
#define ML 512

// Scratch (no cudaMalloc allowed) — [B,H,S,D] layout for Q/K/V, [B*S,E] for AO.
__device__ float g_Q[BB*HH*SS*DD];
__device__ float g_K[BB*HH*SS*DD];
__device__ float g_V[BB*HH*SS*DD];
__device__ float g_AO[BB*SS*EE];

// ---------------------------------------------------------------------------
// Kernel 1: QKV projections.  C[4096,768] = X @ W, written transposed to
// [B,H,S,D].  64x64 block tile, BK=16, 256 threads, 4x4 micro-tile/thread.
// ---------------------------------------------------------------------------
__global__ void qkv_gemm_kernel(const float* __restrict__ x,
                                const float* __restrict__ Wq,
                                const float* __restrict__ Wk,
                                const float* __restrict__ Wv) {
    const float* W = (blockIdx.z == 0) ? Wq : (blockIdx.z == 1 ? Wk : Wv);
    float* out = (blockIdx.z == 0) ? g_Q : (blockIdx.z == 1 ? g_K : g_V);

    __shared__ float As[64][17];   // padded: conflict-free column reads
    __shared__ float Bs[16][64];

    const int rowBase = blockIdx.y * 64;
    const int colBase = blockIdx.x * 64;
    const int tid = threadIdx.x;
    const int tx = tid & 15;
    const int ty = tid >> 4;

    float acc[4][4] = {};

    for (int k0 = 0; k0 < EE; k0 += 16) {
        {   // As: 64x16, one float4 per thread
            int r = tid >> 2, c4 = (tid & 3) * 4;
            float4 v = *reinterpret_cast<const float4*>(x + (size_t)(rowBase + r) * EE + k0 + c4);
            As[r][c4] = v.x; As[r][c4+1] = v.y; As[r][c4+2] = v.z; As[r][c4+3] = v.w;
        }
        {   // Bs: 16x64, one float4 per thread
            int r = tid >> 4, c4 = (tid & 15) * 4;
            float4 v = *reinterpret_cast<const float4*>(W + (size_t)(k0 + r) * EE + colBase + c4);
            *reinterpret_cast<float4*>(&Bs[r][c4]) = v;
        }
        __syncthreads();
        #pragma unroll
        for (int kk = 0; kk < 16; kk++) {
            float a[4], b[4];
            #pragma unroll
            for (int i = 0; i < 4; i++) a[i] = As[ty + 16*i][kk];
            #pragma unroll
            for (int j = 0; j < 4; j++) b[j] = Bs[kk][tx + 16*j];
            #pragma unroll
            for (int i = 0; i < 4; i++)
                #pragma unroll
                for (int j = 0; j < 4; j++)
                    acc[i][j] += a[i] * b[j];
        }
        __syncthreads();
    }

    #pragma unroll
    for (int i = 0; i < 4; i++) {
        int row = rowBase + ty + 16*i;
        int b_  = row >> 9;          // /512
        int s_  = row & 511;
        #pragma unroll
        for (int j = 0; j < 4; j++) {
            int col = colBase + tx + 16*j;
            int h_ = col >> 6;       // /64
            int d_ = col & 63;
            out[(((size_t)b_ * HH + h_) * SS + s_) * DD + d_] = acc[i][j];
        }
    }
}

// ---------------------------------------------------------------------------
// Kernel 2: attention.  One CTA per (b, h, 64-query tile).
// Scores panel 64x512 kept in dynamic smem; fused bias + mask + softmax + P@V.
// ---------------------------------------------------------------------------
__global__ void attn_kernel(const float* __restrict__ rel_pos,
                            const int* __restrict__ mask) {
    extern __shared__ float sm[];
    float* Qs  = sm;                  // 64*65
    float* KVs = sm + 64 * 65;        // 64*65
    float* P   = sm + 2 * 64 * 65;    // 64*512

    const int qt = blockIdx.x;        // 0..7
    const int bh = blockIdx.y;        // 0..95
    const int b_ = bh / HH;
    const int h_ = bh % HH;
    const int q0 = qt * 64;

    const int tid  = threadIdx.x;
    const int tx   = tid & 15;
    const int ty   = tid >> 4;
    const int lane = tid & 31;
    const int wid  = tid >> 5;

    const float* Qg = g_Q + (size_t)bh * SS * DD;
    const float* Kg = g_K + (size_t)bh * SS * DD;
    const float* Vg = g_V + (size_t)bh * SS * DD;

    // Load Q tile [64][64] (padded stride 65)
    for (int i = tid; i < 64 * 16; i += 256) {
        int r = i >> 4, c4 = (i & 15) * 4;
        float4 v = *reinterpret_cast<const float4*>(Qg + (size_t)(q0 + r) * DD + c4);
        Qs[r*65 + c4] = v.x; Qs[r*65 + c4+1] = v.y; Qs[r*65 + c4+2] = v.z; Qs[r*65 + c4+3] = v.w;
    }
    __syncthreads();

    // ---- scores = Q @ K^T * 1/8 + bias, masked ----
    for (int kt = 0; kt < 8; kt++) {
        for (int i = tid; i < 64 * 16; i += 256) {
            int r = i >> 4, c4 = (i & 15) * 4;
            float4 v = *reinterpret_cast<const float4*>(Kg + (size_t)(kt*64 + r) * DD + c4);
            KVs[r*65 + c4] = v.x; KVs[r*65 + c4+1] = v.y; KVs[r*65 + c4+2] = v.z; KVs[r*65 + c4+3] = v.w;
        }
        __syncthreads();

        float acc[4][4] = {};
        #pragma unroll
        for (int dd = 0; dd < 64; dd++) {
            float a[4], bv[4];
            #pragma unroll
            for (int i = 0; i < 4; i++) a[i]  = Qs[(ty + 16*i)*65 + dd];
            #pragma unroll
            for (int j = 0; j < 4; j++) bv[j] = KVs[(tx + 16*j)*65 + dd];
            #pragma unroll
            for (int i = 0; i < 4; i++)
                #pragma unroll
                for (int j = 0; j < 4; j++)
                    acc[i][j] += a[i] * bv[j];
        }

        #pragma unroll
        for (int i = 0; i < 4; i++) {
            int q  = ty + 16*i;
            int qg = q0 + q;
            int mq = mask[b_ * SS + qg];
            #pragma unroll
            for (int j = 0; j < 4; j++) {
                int k  = tx + 16*j;
                int kg = kt * 64 + k;
                int idx = kg - qg + (ML - 1);
                idx = idx < 0 ? 0 : (idx > 2*ML - 2 ? 2*ML - 2 : idx);
                float v = acc[i][j] * 0.125f + rel_pos[idx * HH + h_];
                int mk = mask[b_ * SS + kg];
                if (mq == 0 || mk == 0) v = -FLT_MAX;
                P[q * 512 + kg] = v;
            }
        }
        __syncthreads();
    }

    // ---- softmax (one warp per row, 8 rows per warp) ----
    for (int r = wid; r < 64; r += 8) {
        float m = -FLT_MAX;
        for (int c = lane; c < 512; c += 32) m = fmaxf(m, P[r*512 + c]);
        #pragma unroll
        for (int o = 16; o > 0; o >>= 1) m = fmaxf(m, __shfl_xor_sync(0xffffffffu, m, o));
        float s = 0.f;
        for (int c = lane; c < 512; c += 32) {
            float e = expf(P[r*512 + c] - m);
            P[r*512 + c] = e;
            s += e;
        }
        #pragma unroll
        for (int o = 16; o > 0; o >>= 1) s += __shfl_xor_sync(0xffffffffu, s, o);
        float inv = 1.0f / s;
        for (int c = lane; c < 512; c += 32) P[r*512 + c] *= inv;
    }
    __syncthreads();

    // ---- out = P @ V ----
    float acc2[4][4] = {};
    for (int vt = 0; vt < 8; vt++) {
        for (int i = tid; i < 64 * 16; i += 256) {
            int r = i >> 4, c4 = (i & 15) * 4;
            float4 v = *reinterpret_cast<const float4*>(Vg + (size_t)(vt*64 + r) * DD + c4);
            KVs[r*65 + c4] = v.x; KVs[r*65 + c4+1] = v.y; KVs[r*65 + c4+2] = v.z; KVs[r*65 + c4+3] = v.w;
        }
        __syncthreads();

        #pragma unroll
        for (int kk = 0; kk < 64; kk++) {
            float p[4], vv[4];
            #pragma unroll
            for (int i = 0; i < 4; i++) p[i]  = P[(ty + 16*i)*512 + vt*64 + kk];
            #pragma unroll
            for (int j = 0; j < 4; j++) vv[j] = KVs[kk*65 + tx + 16*j];
            #pragma unroll
            for (int i = 0; i < 4; i++)
                #pragma unroll
                for (int j = 0; j < 4; j++)
                    acc2[i][j] += p[i] * vv[j];
        }
        __syncthreads();
    }

    #pragma unroll
    for (int i = 0; i < 4; i++) {
        int qg = q0 + ty + 16*i;
        #pragma unroll
        for (int j = 0; j < 4; j++) {
            int d_ = tx + 16*j;
            g_AO[((size_t)b_ * SS + qg) * EE + h_ * DD + d_] = acc2[i][j];
        }
    }
}

// ---------------------------------------------------------------------------
// Kernel 3: output projection with bias.  out[4096,768] = AO @ Wo + bo
// ---------------------------------------------------------------------------
__global__ void out_gemm_kernel(const float* __restrict__ Wo,
                                const float* __restrict__ bo,
                                float* __restrict__ out) {
    __shared__ float As[64][17];
    __shared__ float Bs[16][64];

    const int rowBase = blockIdx.y * 64;
    const int colBase = blockIdx.x * 64;
    const int tid = threadIdx.x;
    const int tx = tid & 15;
    const int ty = tid >> 4;

    float acc[4][4] = {};

    for (int k0 = 0; k0 < EE; k0 += 16) {
        {
            int r = tid >> 2, c4 = (tid & 3) * 4;
            float4 v = *reinterpret_cast<const float4*>(g_AO + (size_t)(rowBase + r) * EE + k0 + c4);
            As[r][c4] = v.x; As[r][c4+1] = v.y; As[r][c4+2] = v.z; As[r][c4+3] = v.w;
        }
        {
            int r = tid >> 4, c4 = (tid & 15) * 4;
            float4 v = *reinterpret_cast<const float4*>(Wo + (size_t)(k0 + r) * EE + colBase + c4);
            *reinterpret_cast<float4*>(&Bs[r][c4]) = v;
        }
        __syncthreads();
        #pragma unroll
        for (int kk = 0; kk < 16; kk++) {
            float a[4], b[4];
            #pragma unroll
            for (int i = 0; i < 4; i++) a[i] = As[ty + 16*i][kk];
            #pragma unroll
            for (int j = 0; j < 4; j++) b[j] = Bs[kk][tx + 16*j];
            #pragma unroll
            for (int i = 0; i < 4; i++)
                #pragma unroll
                for (int j = 0; j < 4; j++)
                    acc[i][j] += a[i] * b[j];
        }
        __syncthreads();
    }

    #pragma unroll
    for (int i = 0; i < 4; i++) {
        int row = rowBase + ty + 16*i;
        #pragma unroll
        for (int j = 0; j < 4; j++) {
            int col = colBase + tx + 16*j;
            out[(size_t)row * EE + col] = acc[i][j] + bo[col];
        }
    }
}

// ---------------------------------------------------------------------------
// Launch
// ---------------------------------------------------------------------------
extern "C" void kernel_launch(void* const* d_in, const int* in_sizes, int n_in,
                              void* d_out, int out_size) {
    const float* x       = (const float*)d_in[0];
    const int*   mask    = (const int*)  d_in[1];
    const float* Wq      = (const float*)d_in[2];
    const float* Wk      = (const float*)d_in[3];
    const float* Wv      = (const float*)d_in[4];
    const float* rel_pos = (const float*)d_in[5];
    const float* Wo      = (const float*)d_in[6];
    const float* bo      = (const float*)d_in[7];
    float* out = (float*)d_out;

    dim3 blk(256);

    // 1) QKV projections
    qkv_gemm_kernel<<<dim3(EE/64, (BB*SS)/64, 3), blk>>>(x, Wq, Wk, Wv);

    // 2) fused attention
    size_t shbytes = (size_t)(2 * 64 * 65 + 64 * 512) * sizeof(float);  // 164,352 B
    cudaFuncSetAttribute(attn_kernel, cudaFuncAttributeMaxDynamicSharedMemorySize,
                         (int)shbytes);
    attn_kernel<<<dim3(8, BB*HH), blk, shbytes>>>(rel_pos, mask);

    // 3) output projection + bias
    out_gemm_kernel<<<dim3(EE/64, (BB*SS)/64), blk>>>(Wo, bo, out);
}

// round 3
// speedup vs baseline: 1.8263x; 1.8263x over previous
#include <cuda_runtime.h>
#include <math.h>
#include <float.h>
#include <stdint.h>

#define BB 8
#define SS 512
#define EE 768
#define HH 12
#define DD 64
#define ML 512
#define PSTR 516

// Scratch (no cudaMalloc allowed)
__device__ float g_Q[BB*HH*SS*DD];
__device__ float g_K[BB*HH*SS*DD];
__device__ float g_V[BB*HH*SS*DD];
__device__ float g_AO[BB*SS*EE];

// ---------------------------------------------------------------------------
// Warp-MMA helpers (sm_80-baseline tf32 path; no arch-suffix features)
// ---------------------------------------------------------------------------
__device__ __forceinline__ uint32_t cvt_tf32(float x) {
    uint32_t u;
    asm("cvt.rna.tf32.f32 %0, %1;" : "=r"(u) : "f"(x));
    return u;
}

__device__ __forceinline__ void mma8(float c[4], const uint32_t a[4],
                                     uint32_t b0, uint32_t b1) {
    asm volatile(
        "mma.sync.aligned.m16n8k8.row.col.f32.tf32.tf32.f32 "
        "{%0,%1,%2,%3},{%4,%5,%6,%7},{%8,%9},{%0,%1,%2,%3};"
        : "+f"(c[0]), "+f"(c[1]), "+f"(c[2]), "+f"(c[3])
        : "r"(a[0]), "r"(a[1]), "r"(a[2]), "r"(a[3]), "r"(b0), "r"(b1));
}

// Fragment-packed smem layouts:
//  A quads : offset = ((ks*MT + mt)*32 + lane)*4 + reg
//            reg = ((r>>3)&1) + (((c>>2)&1)<<1), lane = (r&7)*4 + (c&3)
//  B pairs : offset = ((ks*NP + pr)*32 + lane)*4 + slot*2 + reg
//            pr = n>>4, slot=(n>>3)&1, lane=(n&7)*4+(c&3), reg=(c>>2)&1

// ---------------------------------------------------------------------------
// Dense GEMM mainloop: C[128,128] tile of A(Mx768) @ W(768x768)
// 128 threads (4 warps, 2x2).  acc[4][8][4] per warp (64 rows x 64 cols).
// ---------------------------------------------------------------------------
__device__ __forceinline__ void g_loadA(const float* __restrict__ A,
                                        int rowBase, int k0, uint32_t* buf, int tid) {
    #pragma unroll
    for (int p = 0; p < 8; p++) {
        int t = tid + p * 128;
        int r = t >> 3, c4 = (t & 7) * 4;
        float4 v = *reinterpret_cast<const float4*>(A + (size_t)(rowBase + r) * EE + k0 + c4);
        uint32_t q[4] = {cvt_tf32(v.x), cvt_tf32(v.y), cvt_tf32(v.z), cvt_tf32(v.w)};
        int mt = r >> 4, rb = (r >> 3) & 1, lb = (r & 7) * 4;
        #pragma unroll
        for (int j = 0; j < 4; j++) {
            int c = c4 + j;
            buf[(((c >> 3) * 8 + mt) * 32 + lb + (c & 3)) * 4 + rb + (((c >> 2) & 1) << 1)] = q[j];
        }
    }
}

__device__ __forceinline__ void g_loadB(const float* __restrict__ W,
                                        int colBase, int k0, uint32_t* buf, int tid) {
    #pragma unroll
    for (int p = 0; p < 8; p++) {
        int t = tid + p * 128;
        int c = t >> 5, n4 = (t & 31) * 4;
        float4 v = *reinterpret_cast<const float4*>(W + (size_t)(k0 + c) * EE + colBase + n4);
        uint32_t q[4] = {cvt_tf32(v.x), cvt_tf32(v.y), cvt_tf32(v.z), cvt_tf32(v.w)};
        int ks = c >> 3, reg = (c >> 2) & 1, cb = c & 3;
        #pragma unroll
        for (int j = 0; j < 4; j++) {
            int n = n4 + j;
            buf[((ks * 8 + (n >> 4)) * 32 + (n & 7) * 4 + cb) * 4 + ((n >> 3) & 1) * 2 + reg] = q[j];
        }
    }
}

__device__ __forceinline__ void g_compute(const uint32_t* bufA, const uint32_t* bufB,
                                          float acc[4][8][4], int lane, int wm, int wn) {
    #pragma unroll
    for (int ks = 0; ks < 4; ks++) {
        uint32_t af[4][4], bf[4][4];
        #pragma unroll
        for (int i = 0; i < 4; i++)
            *reinterpret_cast<uint4*>(af[i]) =
                *reinterpret_cast<const uint4*>(bufA + ((ks * 8 + wm * 4 + i) * 32 + lane) * 4);
        #pragma unroll
        for (int j = 0; j < 4; j++)
            *reinterpret_cast<uint4*>(bf[j]) =
                *reinterpret_cast<const uint4*>(bufB + ((ks * 8 + wn * 4 + j) * 32 + lane) * 4);
        #pragma unroll
        for (int i = 0; i < 4; i++)
            #pragma unroll
            for (int j = 0; j < 4; j++) {
                mma8(acc[i][2*j],   af[i], bf[j][0], bf[j][1]);
                mma8(acc[i][2*j+1], af[i], bf[j][2], bf[j][3]);
            }
    }
}

__device__ __forceinline__ void gemm_mainloop(const float* __restrict__ A,
                                              const float* __restrict__ W,
                                              int rowBase, int colBase,
                                              uint32_t* sm, float acc[4][8][4],
                                              int tid, int lane, int wm, int wn) {
    uint32_t* Af[2] = {sm, sm + 8192};
    uint32_t* Bf[2] = {sm + 4096, sm + 12288};
    g_loadA(A, rowBase, 0, Af[0], tid);
    g_loadB(W, colBase, 0, Bf[0], tid);
    __syncthreads();
    for (int c = 0; c < 24; c++) {
        int cur = c & 1;
        if (c + 1 < 24) {
            g_loadA(A, rowBase, (c + 1) * 32, Af[cur ^ 1], tid);
            g_loadB(W, colBase, (c + 1) * 32, Bf[cur ^ 1], tid);
        }
        g_compute(Af[cur], Bf[cur], acc, lane, wm, wn);
        __syncthreads();
    }
}

// ---------------------------------------------------------------------------
// Kernel 1: QKV projections.  grid (6,32,3), 128 threads, 64KB smem
// ---------------------------------------------------------------------------
__global__ void __launch_bounds__(128)
qkv_mma_kernel(const float* __restrict__ x, const float* __restrict__ Wq,
               const float* __restrict__ Wk, const float* __restrict__ Wv) {
    extern __shared__ uint32_t sm[];
    const int tid = threadIdx.x, lane = tid & 31, wid = tid >> 5;
    const int wm = wid & 1, wn = wid >> 1;
    const float* W = (blockIdx.z == 0) ? Wq : (blockIdx.z == 1 ? Wk : Wv);
    float* out = (blockIdx.z == 0) ? g_Q : (blockIdx.z == 1 ? g_K : g_V);
    const int rowBase = blockIdx.y * 128, colBase = blockIdx.x * 128;

    float acc[4][8][4] = {};
    gemm_mainloop(x, W, rowBase, colBase, sm, acc, tid, lane, wm, wn);

    #pragma unroll
    for (int i = 0; i < 4; i++) {
        int r0 = rowBase + (wm * 4 + i) * 16 + (lane >> 2);
        #pragma unroll
        for (int j = 0; j < 4; j++)
            #pragma unroll
            for (int slot = 0; slot < 2; slot++) {
                int jj = 2 * j + slot;
                int col = colBase + (wn * 4 + j) * 16 + slot * 8 + (lane & 3) * 2;
                int h_ = col >> 6, d_ = col & 63;
                {
                    int b_ = r0 >> 9, s_ = r0 & 511;
                    float2 v = make_float2(acc[i][jj][0], acc[i][jj][1]);
                    *reinterpret_cast<float2*>(out + (((size_t)b_ * HH + h_) * SS + s_) * DD + d_) = v;
                }
                {
                    int r1 = r0 + 8;
                    int b_ = r1 >> 9, s_ = r1 & 511;
                    float2 v = make_float2(acc[i][jj][2], acc[i][jj][3]);
                    *reinterpret_cast<float2*>(out + (((size_t)b_ * HH + h_) * SS + s_) * DD + d_) = v;
                }
            }
    }
}

// ---------------------------------------------------------------------------
// Kernel 3: output projection + bias.  grid (6,32), 128 threads
// ---------------------------------------------------------------------------
__global__ void __launch_bounds__(128)
out_mma_kernel(const float* __restrict__ Wo, const float* __restrict__ bo,
               float* __restrict__ out) {
    extern __shared__ uint32_t sm[];
    const int tid = threadIdx.x, lane = tid & 31, wid = tid >> 5;
    const int wm = wid & 1, wn = wid >> 1;
    const int rowBase = blockIdx.y * 128, colBase = blockIdx.x * 128;

    float acc[4][8][4] = {};
    gemm_mainloop(g_AO, Wo, rowBase, colBase, sm, acc, tid, lane, wm, wn);

    #pragma unroll
    for (int i = 0; i < 4; i++) {
        int r0 = rowBase + (wm * 4 + i) * 16 + (lane >> 2);
        #pragma unroll
        for (int j = 0; j < 4; j++)
            #pragma unroll
            for (int slot = 0; slot < 2; slot++) {
                int jj = 2 * j + slot;
                int col = colBase + (wn * 4 + j) * 16 + slot * 8 + (lane & 3) * 2;
                float b0v = bo[col], b1v = bo[col + 1];
                *reinterpret_cast<float2*>(out + (size_t)r0 * EE + col) =
                    make_float2(acc[i][jj][0] + b0v, acc[i][jj][1] + b1v);
                *reinterpret_cast<float2*>(out + (size_t)(r0 + 8) * EE + col) =
                    make_float2(acc[i][jj][2] + b0v, acc[i][jj][3] + b1v);
            }
    }
}

// ---------------------------------------------------------------------------
// Kernel 2: attention with warp-MMA.  grid (8, 96), 256 threads.
// smem: P[64][516] fp32 | Qf (A-frags) | KV frag chunks x2 | mask row
// ---------------------------------------------------------------------------
#define AT_P    0
#define AT_QF   33024
#define AT_KV0  37120
#define AT_KV1  45312
#define AT_MASK 53504
#define AT_FLOATS (53504 + 512)

__device__ __forceinline__ void at_loadQ(const float* __restrict__ Qg, int q0,
                                         uint32_t* Qf, int tid) {
    #pragma unroll
    for (int p = 0; p < 4; p++) {
        int t = tid + p * 256;
        int r = t >> 4, d4 = (t & 15) * 4;
        float4 v = *reinterpret_cast<const float4*>(Qg + (size_t)(q0 + r) * DD + d4);
        uint32_t q[4] = {cvt_tf32(v.x), cvt_tf32(v.y), cvt_tf32(v.z), cvt_tf32(v.w)};
        int mt = r >> 4, rb = (r >> 3) & 1, lb = (r & 7) * 4;
        #pragma unroll
        for (int j = 0; j < 4; j++) {
            int d = d4 + j;
            Qf[(((d >> 3) * 4 + mt) * 32 + lb + (d & 3)) * 4 + rb + (((d >> 2) & 1) << 1)] = q[j];
        }
    }
}

// K chunk as B-frags for QK^T:  k-dim = d (8 ksteps), n-dim = kpos (8 pairs)
__device__ __forceinline__ void at_loadK(const float* __restrict__ Kg, int kc,
                                         uint32_t* buf, int tid) {
    #pragma unroll
    for (int p = 0; p < 8; p++) {
        int t = tid + p * 256;
        int kp = t >> 4, d4 = (t & 15) * 4;
        float4 v = *reinterpret_cast<const float4*>(Kg + (size_t)(kc * 128 + kp) * DD + d4);
        uint32_t q[4] = {cvt_tf32(v.x), cvt_tf32(v.y), cvt_tf32(v.z), cvt_tf32(v.w)};
        int pr = kp >> 4, slot = (kp >> 3) & 1, lb = (kp & 7) * 4;
        #pragma unroll
        for (int j = 0; j < 4; j++) {
            int d = d4 + j;
            buf[(((d >> 3) * 8 + pr) * 32 + lb + (d & 3)) * 4 + slot * 2 + ((d >> 2) & 1)] = q[j];
        }
    }
}

// V chunk as B-frags for P@V:  k-dim = kpos (16 ksteps), n-dim = d (4 pairs)
__device__ __forceinline__ void at_loadV(const float* __restrict__ Vg, int kc,
                                         uint32_t* buf, int tid) {
    #pragma unroll
    for (int p = 0; p < 8; p++) {
        int t = tid + p * 256;
        int kp = t >> 4, d4 = (t & 15) * 4;
        float4 v = *reinterpret_cast<const float4*>(Vg + (size_t)(kc * 128 + kp) * DD + d4);
        uint32_t q[4] = {cvt_tf32(v.x), cvt_tf32(v.y), cvt_tf32(v.z), cvt_tf32(v.w)};
        int ks = kp >> 3, reg = (kp >> 2) & 1, cb = kp & 3;
        #pragma unroll
        for (int j = 0; j < 4; j++) {
            int d = d4 + j;
            buf[((ks * 4 + (d >> 4)) * 32 + (d & 7) * 4 + cb) * 4 + ((d >> 3) & 1) * 2 + reg] = q[j];
        }
    }
}

__global__ void __launch_bounds__(256)
attn_mma_kernel(const float* __restrict__ rel_pos, const int* __restrict__ mask) {
    extern __shared__ float smf[];
    float* P = smf + AT_P;
    uint32_t* Qf = reinterpret_cast<uint32_t*>(smf + AT_QF);
    uint32_t* KV[2] = {reinterpret_cast<uint32_t*>(smf + AT_KV0),
                       reinterpret_cast<uint32_t*>(smf + AT_KV1)};
    int* maskS = reinterpret_cast<int*>(smf + AT_MASK);

    const int qt = blockIdx.x, bh = blockIdx.y;
    const int b_ = bh / HH, h_ = bh % HH;
    const int q0 = qt * 64;
    const int tid = threadIdx.x, lane = tid & 31, wid = tid >> 5;

    const float* Qg = g_Q + (size_t)bh * SS * DD;
    const float* Kg = g_K + (size_t)bh * SS * DD;
    const float* Vg = g_V + (size_t)bh * SS * DD;

    maskS[tid] = mask[b_ * SS + tid];
    maskS[tid + 256] = mask[b_ * SS + tid + 256];

    at_loadQ(Qg, q0, Qf, tid);
    at_loadK(Kg, 0, KV[0], tid);
    __syncthreads();

    // ---- QK^T -> P (with scale, bias, mask) ----
    {
        const int wm = wid >> 2, wn = wid & 3;   // 2 x 4 warps; warp tile 32x32
        for (int kc = 0; kc < 4; kc++) {
            int cur = kc & 1;
            if (kc + 1 < 4) at_loadK(Kg, kc + 1, KV[cur ^ 1], tid);

            float acc[2][4][4] = {};
            #pragma unroll
            for (int ks = 0; ks < 8; ks++) {
                uint32_t af[2][4], bf[2][4];
                #pragma unroll
                for (int i = 0; i < 2; i++)
                    *reinterpret_cast<uint4*>(af[i]) = *reinterpret_cast<const uint4*>(
                        Qf + ((ks * 4 + wm * 2 + i) * 32 + lane) * 4);
                #pragma unroll
                for (int j = 0; j < 2; j++)
                    *reinterpret_cast<uint4*>(bf[j]) = *reinterpret_cast<const uint4*>(
                        KV[cur] + ((ks * 8 + wn * 2 + j) * 32 + lane) * 4);
                #pragma unroll
                for (int i = 0; i < 2; i++)
                    #pragma unroll
                    for (int j = 0; j < 2; j++) {
                        mma8(acc[i][2*j],   af[i], bf[j][0], bf[j][1]);
                        mma8(acc[i][2*j+1], af[i], bf[j][2], bf[j][3]);
                    }
            }

            #pragma unroll
            for (int i = 0; i < 2; i++) {
                int qr0 = wm * 32 + i * 16 + (lane >> 2);
                #pragma unroll
                for (int jj = 0; jj < 4; jj++) {
                    int kpos = kc * 128 + (wn * 4 + jj) * 8 + (lane & 3) * 2;
                    #pragma unroll
                    for (int half = 0; half < 2; half++) {
                        int qr = qr0 + half * 8;
                        int qg = q0 + qr;
                        int mq = maskS[qg];
                        float v0 = acc[i][jj][half*2]   * 0.125f;
                        float v1 = acc[i][jj][half*2+1] * 0.125f;
                        int i0 = kpos     - qg + (ML - 1);
                        int i1 = kpos + 1 - qg + (ML - 1);
                        i0 = i0 < 0 ? 0 : (i0 > 2*ML-2 ? 2*ML-2 : i0);
                        i1 = i1 < 0 ? 0 : (i1 > 2*ML-2 ? 2*ML-2 : i1);
                        v0 += rel_pos[i0 * HH + h_];
                        v1 += rel_pos[i1 * HH + h_];
                        if (mq == 0 || maskS[kpos]     == 0) v0 = -FLT_MAX;
                        if (mq == 0 || maskS[kpos + 1] == 0) v1 = -FLT_MAX;
                        *reinterpret_cast<float2*>(P + qr * PSTR + kpos) = make_float2(v0, v1);
                    }
                }
            }
            __syncthreads();
        }
    }

    // ---- softmax (one warp per row, 8 rows per warp) ----
    for (int r = wid; r < 64; r += 8) {
        float m = -FLT_MAX;
        #pragma unroll
        for (int c = 0; c < 16; c++) m = fmaxf(m, P[r * PSTR + lane + c * 32]);
        #pragma unroll
        for (int o = 16; o > 0; o >>= 1) m = fmaxf(m, __shfl_xor_sync(0xffffffffu, m, o));
        float s = 0.f;
        #pragma unroll
        for (int c = 0; c < 16; c++) {
            float e = __expf(P[r * PSTR + lane + c * 32] - m);
            P[r * PSTR + lane + c * 32] = e;
            s += e;
        }
        #pragma unroll
        for (int o = 16; o > 0; o >>= 1) s += __shfl_xor_sync(0xffffffffu, s, o);
        float inv = 1.0f / s;
        #pragma unroll
        for (int c = 0; c < 16; c++) P[r * PSTR + lane + c * 32] *= inv;
    }
    __syncthreads();

    // ---- out = P @ V ----
    {
        const int wm = wid >> 1, wn = wid & 1;   // 4 x 2 warps; warp tile 16x32
        float acc2[4][4] = {};
        at_loadV(Vg, 0, KV[0], tid);
        __syncthreads();
        for (int kc = 0; kc < 4; kc++) {
            int cur = kc & 1;
            if (kc + 1 < 4) at_loadV(Vg, kc + 1, KV[cur ^ 1], tid);

            const int row0 = wm * 16 + (lane >> 2);
            #pragma unroll
            for (int ks = 0; ks < 16; ks++) {
                int ck = kc * 128 + ks * 8 + (lane & 3);
                uint32_t a[4];
                a[0] = cvt_tf32(P[row0 * PSTR + ck]);
                a[1] = cvt_tf32(P[(row0 + 8) * PSTR + ck]);
                a[2] = cvt_tf32(P[row0 * PSTR + ck + 4]);
                a[3] = cvt_tf32(P[(row0 + 8) * PSTR + ck + 4]);
                uint32_t bf[2][4];
                #pragma unroll
                for (int j = 0; j < 2; j++)
                    *reinterpret_cast<uint4*>(bf[j]) = *reinterpret_cast<const uint4*>(
                        KV[cur] + ((ks * 4 + wn * 2 + j) * 32 + lane) * 4);
                #pragma unroll
                for (int j = 0; j < 2; j++) {
                    mma8(acc2[2*j],   a, bf[j][0], bf[j][1]);
                    mma8(acc2[2*j+1], a, bf[j][2], bf[j][3]);
                }
            }
            __syncthreads();
        }

        #pragma unroll
        for (int jj = 0; jj < 4; jj++) {
            int d_ = wn * 32 + jj * 8 + (lane & 3) * 2;
            int q_ = q0 + wm * 16 + (lane >> 2);
            *reinterpret_cast<float2*>(g_AO + ((size_t)b_ * SS + q_) * EE + h_ * DD + d_) =
                make_float2(acc2[jj][0], acc2[jj][1]);
            *reinterpret_cast<float2*>(g_AO + ((size_t)b_ * SS + q_ + 8) * EE + h_ * DD + d_) =
                make_float2(acc2[jj][2], acc2[jj][3]);
        }
    }
}

// ---------------------------------------------------------------------------
// Launch
// ---------------------------------------------------------------------------
extern "C" void kernel_launch(void* const* d_in, const int* in_sizes, int n_in,
                              void* d_out, int out_size) {
    const float* x       = (const float*)d_in[0];
    const int*   mask    = (const int*)  d_in[1];
    const float* Wq      = (const float*)d_in[2];
    const float* Wk      = (const float*)d_in[3];
    const float* Wv      = (const float*)d_in[4];
    const float* rel_pos = (const float*)d_in[5];
    const float* Wo      = (const float*)d_in[6];
    const float* bo      = (const float*)d_in[7];
    float* out = (float*)d_out;

    const int gemm_smem = 16384 * sizeof(uint32_t);          // 64 KB
    const int attn_smem = AT_FLOATS * sizeof(float);          // ~211 KB

    cudaFuncSetAttribute(qkv_mma_kernel, cudaFuncAttributeMaxDynamicSharedMemorySize, gemm_smem);
    cudaFuncSetAttribute(out_mma_kernel, cudaFuncAttributeMaxDynamicSharedMemorySize, gemm_smem);
    cudaFuncSetAttribute(attn_mma_kernel, cudaFuncAttributeMaxDynamicSharedMemorySize, attn_smem);

    qkv_mma_kernel<<<dim3(EE/128, (BB*SS)/128, 3), 128, gemm_smem>>>(x, Wq, Wk, Wv);
    attn_mma_kernel<<<dim3(8, BB*HH), 256, attn_smem>>>(rel_pos, mask);
    out_mma_kernel<<<dim3(EE/128, (BB*SS)/128), 128, gemm_smem>>>(Wo, bo, out);
}

// round 4
// speedup vs baseline: 3.1510x; 1.7254x over previous
#include <cuda_runtime.h>
#include <math.h>
#include <float.h>
#include <stdint.h>

#define BB 8
#define SS 512
#define EE 768
#define HH 12
#define DD 64
#define ML 512
#define PSTR 516

// Scratch (no cudaMalloc allowed)
__device__ float g_Q[BB*HH*SS*DD];
__device__ float g_K[BB*HH*SS*DD];
__device__ float g_V[BB*HH*SS*DD];
__device__ float g_AO[BB*SS*EE];

// ---------------------------------------------------------------------------
// Helpers
// ---------------------------------------------------------------------------
__device__ __forceinline__ uint32_t smem_u32(const void* p) {
    uint32_t a;
    asm("{ .reg .u64 t; cvta.to.shared.u64 t, %1; cvt.u32.u64 %0, t; }"
        : "=r"(a) : "l"(p));
    return a;
}

__device__ __forceinline__ uint32_t cvt_tf32(float x) {
    uint32_t u;
    asm("cvt.rna.tf32.f32 %0, %1;" : "=r"(u) : "f"(x));
    return u;
}

__device__ __forceinline__ void mma8(float c[4], const uint32_t a[4],
                                     uint32_t b0, uint32_t b1) {
    asm volatile(
        "mma.sync.aligned.m16n8k8.row.col.f32.tf32.tf32.f32 "
        "{%0,%1,%2,%3},{%4,%5,%6,%7},{%8,%9},{%0,%1,%2,%3};"
        : "+f"(c[0]), "+f"(c[1]), "+f"(c[2]), "+f"(c[3])
        : "r"(a[0]), "r"(a[1]), "r"(a[2]), "r"(a[3]), "r"(b0), "r"(b1));
}

__device__ __forceinline__ void cp16(uint32_t dst, const void* src) {
    asm volatile("cp.async.ca.shared.global [%0], [%1], 16;"
                 :: "r"(dst), "l"(src) : "memory");
}
__device__ __forceinline__ void cp_commit() {
    asm volatile("cp.async.commit_group;" ::: "memory");
}
__device__ __forceinline__ void cp_wait1() {
    asm volatile("cp.async.wait_group 1;" ::: "memory");
}
__device__ __forceinline__ void cp_wait0() {
    asm volatile("cp.async.wait_group 0;" ::: "memory");
}

// ---------------------------------------------------------------------------
// Dense GEMM: C[128,128] tile of A(Mx768) @ W(768x768), 128 threads (2x2 warps)
// smem (floats): A0[0,4608) A1[4608,9216) B0[9216,13568) B1[13568,17920)
//   A: [128 rows][stride 36]   (banks: 4r+c  -> conflict-free frag loads)
//   B: [32 k-rows][stride 136] (banks: 8k+n  -> conflict-free frag loads)
// ---------------------------------------------------------------------------
#define G_SMEM_FLOATS 17920

__device__ __forceinline__ void g_loadA_cp(const float* __restrict__ A, int rowBase,
                                           int k0, uint32_t dstb, int tid) {
    #pragma unroll
    for (int p = 0; p < 8; p++) {
        int t = tid + p * 128;
        int r = t >> 3, seg = t & 7;
        cp16(dstb + (uint32_t)(r * 36 + seg * 4) * 4u,
             A + (size_t)(rowBase + r) * EE + k0 + seg * 4);
    }
}
__device__ __forceinline__ void g_loadB_cp(const float* __restrict__ W, int colBase,
                                           int k0, uint32_t dstb, int tid) {
    #pragma unroll
    for (int p = 0; p < 8; p++) {
        int t = tid + p * 128;
        int k = t >> 5, seg = t & 31;
        cp16(dstb + (uint32_t)(k * 136 + seg * 4) * 4u,
             W + (size_t)(k0 + k) * EE + colBase + seg * 4);
    }
}

__device__ __forceinline__ void gemm_mainloop(const float* __restrict__ A,
                                              const float* __restrict__ W,
                                              int rowBase, int colBase,
                                              float* smf, uint32_t smb,
                                              float acc[4][8][4],
                                              int tid, int lane, int wm, int wn) {
    const uint32_t aOff[2] = {smb, smb + 4608u * 4u};
    const uint32_t bOff[2] = {smb + 9216u * 4u, smb + 13568u * 4u};

    g_loadA_cp(A, rowBase, 0, aOff[0], tid);
    g_loadB_cp(W, colBase, 0, bOff[0], tid);
    cp_commit();

    for (int c = 0; c < 24; c++) {
        int cur = c & 1;
        if (c + 1 < 24) {
            g_loadA_cp(A, rowBase, (c + 1) * 32, aOff[cur ^ 1], tid);
            g_loadB_cp(W, colBase, (c + 1) * 32, bOff[cur ^ 1], tid);
            cp_commit();
            cp_wait1();
        } else {
            cp_wait0();
        }
        __syncthreads();

        const float* Ab = smf + (cur ? 4608 : 0);
        const float* Bb = smf + 9216 + (cur ? 4352 : 0);

        #pragma unroll
        for (int ks = 0; ks < 4; ks++) {
            uint32_t af[4][4], bf[4][4];
            #pragma unroll
            for (int i = 0; i < 4; i++) {
                int R = wm * 64 + i * 16 + (lane >> 2);
                int c0 = ks * 8 + (lane & 3);
                af[i][0] = cvt_tf32(Ab[R * 36 + c0]);
                af[i][1] = cvt_tf32(Ab[(R + 8) * 36 + c0]);
                af[i][2] = cvt_tf32(Ab[R * 36 + c0 + 4]);
                af[i][3] = cvt_tf32(Ab[(R + 8) * 36 + c0 + 4]);
            }
            #pragma unroll
            for (int j = 0; j < 4; j++) {
                int n0 = wn * 64 + j * 16 + (lane >> 2);
                int kk = ks * 8 + (lane & 3);
                bf[j][0] = cvt_tf32(Bb[kk * 136 + n0]);
                bf[j][1] = cvt_tf32(Bb[(kk + 4) * 136 + n0]);
                bf[j][2] = cvt_tf32(Bb[kk * 136 + n0 + 8]);
                bf[j][3] = cvt_tf32(Bb[(kk + 4) * 136 + n0 + 8]);
            }
            #pragma unroll
            for (int i = 0; i < 4; i++)
                #pragma unroll
                for (int j = 0; j < 4; j++) {
                    mma8(acc[i][2*j],   af[i], bf[j][0], bf[j][1]);
                    mma8(acc[i][2*j+1], af[i], bf[j][2], bf[j][3]);
                }
        }
        __syncthreads();
    }
}

// ---------------------------------------------------------------------------
// Kernel 1: QKV projections.  grid (6,32,3), 128 threads
// ---------------------------------------------------------------------------
__global__ void __launch_bounds__(128)
qkv_mma_kernel(const float* __restrict__ x, const float* __restrict__ Wq,
               const float* __restrict__ Wk, const float* __restrict__ Wv) {
    extern __shared__ float smf[];
    const uint32_t smb = smem_u32(smf);
    const int tid = threadIdx.x, lane = tid & 31, wid = tid >> 5;
    const int wm = wid & 1, wn = wid >> 1;
    const float* W = (blockIdx.z == 0) ? Wq : (blockIdx.z == 1 ? Wk : Wv);
    float* out = (blockIdx.z == 0) ? g_Q : (blockIdx.z == 1 ? g_K : g_V);
    const int rowBase = blockIdx.y * 128, colBase = blockIdx.x * 128;

    float acc[4][8][4] = {};
    gemm_mainloop(x, W, rowBase, colBase, smf, smb, acc, tid, lane, wm, wn);

    #pragma unroll
    for (int i = 0; i < 4; i++) {
        int r0 = rowBase + (wm * 4 + i) * 16 + (lane >> 2);
        #pragma unroll
        for (int j = 0; j < 4; j++)
            #pragma unroll
            for (int slot = 0; slot < 2; slot++) {
                int jj = 2 * j + slot;
                int col = colBase + (wn * 4 + j) * 16 + slot * 8 + (lane & 3) * 2;
                int h_ = col >> 6, d_ = col & 63;
                {
                    int b_ = r0 >> 9, s_ = r0 & 511;
                    *reinterpret_cast<float2*>(out + (((size_t)b_ * HH + h_) * SS + s_) * DD + d_) =
                        make_float2(acc[i][jj][0], acc[i][jj][1]);
                }
                {
                    int r1 = r0 + 8;
                    int b_ = r1 >> 9, s_ = r1 & 511;
                    *reinterpret_cast<float2*>(out + (((size_t)b_ * HH + h_) * SS + s_) * DD + d_) =
                        make_float2(acc[i][jj][2], acc[i][jj][3]);
                }
            }
    }
}

// ---------------------------------------------------------------------------
// Kernel 3: output projection + bias.  grid (6,32), 128 threads
// ---------------------------------------------------------------------------
__global__ void __launch_bounds__(128)
out_mma_kernel(const float* __restrict__ Wo, const float* __restrict__ bo,
               float* __restrict__ out) {
    extern __shared__ float smf[];
    const uint32_t smb = smem_u32(smf);
    const int tid = threadIdx.x, lane = tid & 31, wid = tid >> 5;
    const int wm = wid & 1, wn = wid >> 1;
    const int rowBase = blockIdx.y * 128, colBase = blockIdx.x * 128;

    float acc[4][8][4] = {};
    gemm_mainloop(g_AO, Wo, rowBase, colBase, smf, smb, acc, tid, lane, wm, wn);

    #pragma unroll
    for (int i = 0; i < 4; i++) {
        int r0 = rowBase + (wm * 4 + i) * 16 + (lane >> 2);
        #pragma unroll
        for (int j = 0; j < 4; j++)
            #pragma unroll
            for (int slot = 0; slot < 2; slot++) {
                int jj = 2 * j + slot;
                int col = colBase + (wn * 4 + j) * 16 + slot * 8 + (lane & 3) * 2;
                float b0v = bo[col], b1v = bo[col + 1];
                *reinterpret_cast<float2*>(out + (size_t)r0 * EE + col) =
                    make_float2(acc[i][jj][0] + b0v, acc[i][jj][1] + b1v);
                *reinterpret_cast<float2*>(out + (size_t)(r0 + 8) * EE + col) =
                    make_float2(acc[i][jj][2] + b0v, acc[i][jj][3] + b1v);
            }
    }
}

// ---------------------------------------------------------------------------
// Kernel 2: attention.  grid (8,96), 256 threads.
// smem floats: P[64*516]=33024 | KV0 @33024 (9216) | KV1 @42240 (9216)
//              | mask(int) @51456 (512)  => 51968 floats = 207,872 B
// K chunks stored [kp][d] stride 68 (banks 4r+c), V stride 72 (banks 8c+r)
// Q pre-converted to registers with 1/8 scale folded in.
// ---------------------------------------------------------------------------
#define AT_KV0 33024
#define AT_KV1 42240
#define AT_MASK 51456
#define AT_FLOATS 51968

__device__ __forceinline__ void at_loadKV_cp(const float* __restrict__ src, int kc,
                                             uint32_t dstb, int stride, int tid) {
    #pragma unroll
    for (int p = 0; p < 8; p++) {
        int t = tid + p * 256;
        int kp = t >> 4, seg = t & 15;
        cp16(dstb + (uint32_t)(kp * stride + seg * 4) * 4u,
             src + (size_t)(kc * 128 + kp) * DD + seg * 4);
    }
}

__global__ void __launch_bounds__(256)
attn_mma_kernel(const float* __restrict__ rel_pos, const int* __restrict__ mask) {
    extern __shared__ float smf[];
    const uint32_t smb = smem_u32(smf);
    float* P = smf;
    const uint32_t kvOff[2] = {smb + AT_KV0 * 4u, smb + AT_KV1 * 4u};
    float* KV[2] = {smf + AT_KV0, smf + AT_KV1};
    int* maskS = reinterpret_cast<int*>(smf + AT_MASK);

    const int qt = blockIdx.x, bh = blockIdx.y;
    const int b_ = bh / HH, h_ = bh % HH;
    const int q0 = qt * 64;
    const int tid = threadIdx.x, lane = tid & 31, wid = tid >> 5;

    const float* Qg = g_Q + (size_t)bh * SS * DD;
    const float* Kg = g_K + (size_t)bh * SS * DD;
    const float* Vg = g_V + (size_t)bh * SS * DD;

    // issue K chunk 0 early
    at_loadKV_cp(Kg, 0, kvOff[0], 68, tid);
    cp_commit();

    // stage Q into P area ([64][68]) + mask
    #pragma unroll
    for (int p = 0; p < 4; p++) {
        int t = tid + p * 256;
        int r = t >> 4, seg = (t & 15) * 4;
        float4 v = *reinterpret_cast<const float4*>(Qg + (size_t)(q0 + r) * DD + seg);
        *reinterpret_cast<float4*>(P + r * 68 + seg) = v;
    }
    maskS[tid] = mask[b_ * SS + tid];
    maskS[tid + 256] = mask[b_ * SS + tid + 256];
    __syncthreads();

    // Q fragments to registers (scale 1/8 folded in)
    const int wmq = wid >> 2, wnq = wid & 3;
    uint32_t qf[8][2][4];
    #pragma unroll
    for (int ks = 0; ks < 8; ks++)
        #pragma unroll
        for (int i = 0; i < 2; i++) {
            int R = wmq * 32 + i * 16 + (lane >> 2);
            int c0 = ks * 8 + (lane & 3);
            qf[ks][i][0] = cvt_tf32(P[R * 68 + c0] * 0.125f);
            qf[ks][i][1] = cvt_tf32(P[(R + 8) * 68 + c0] * 0.125f);
            qf[ks][i][2] = cvt_tf32(P[R * 68 + c0 + 4] * 0.125f);
            qf[ks][i][3] = cvt_tf32(P[(R + 8) * 68 + c0 + 4] * 0.125f);
        }
    __syncthreads();   // P area now free for the score panel

    // ---- QK^T -> P ----
    for (int kc = 0; kc < 4; kc++) {
        int cur = kc & 1;
        if (kc + 1 < 4) {
            at_loadKV_cp(Kg, kc + 1, kvOff[cur ^ 1], 68, tid);
            cp_commit();
            cp_wait1();
        } else {
            cp_wait0();
        }
        __syncthreads();
        const float* Ks = KV[cur];

        float acc[2][4][4] = {};
        #pragma unroll
        for (int ks = 0; ks < 8; ks++) {
            uint32_t bf[2][4];
            #pragma unroll
            for (int j = 0; j < 2; j++) {
                int n0 = wnq * 32 + j * 16 + (lane >> 2);
                int kk = ks * 8 + (lane & 3);
                bf[j][0] = cvt_tf32(Ks[n0 * 68 + kk]);
                bf[j][1] = cvt_tf32(Ks[n0 * 68 + kk + 4]);
                bf[j][2] = cvt_tf32(Ks[(n0 + 8) * 68 + kk]);
                bf[j][3] = cvt_tf32(Ks[(n0 + 8) * 68 + kk + 4]);
            }
            #pragma unroll
            for (int i = 0; i < 2; i++)
                #pragma unroll
                for (int j = 0; j < 2; j++) {
                    mma8(acc[i][2*j],   qf[ks][i], bf[j][0], bf[j][1]);
                    mma8(acc[i][2*j+1], qf[ks][i], bf[j][2], bf[j][3]);
                }
        }

        #pragma unroll
        for (int i = 0; i < 2; i++) {
            int qr0 = wmq * 32 + i * 16 + (lane >> 2);
            #pragma unroll
            for (int jj = 0; jj < 4; jj++) {
                int kpos = kc * 128 + wnq * 32 + jj * 8 + (lane & 3) * 2;
                #pragma unroll
                for (int half = 0; half < 2; half++) {
                    int qr = qr0 + half * 8;
                    int qg = q0 + qr;
                    int mq = maskS[qg];
                    float v0 = acc[i][jj][half*2];
                    float v1 = acc[i][jj][half*2+1];
                    int i0 = kpos     - qg + (ML - 1);
                    int i1 = kpos + 1 - qg + (ML - 1);
                    i0 = i0 < 0 ? 0 : (i0 > 2*ML-2 ? 2*ML-2 : i0);
                    i1 = i1 < 0 ? 0 : (i1 > 2*ML-2 ? 2*ML-2 : i1);
                    v0 += rel_pos[i0 * HH + h_];
                    v1 += rel_pos[i1 * HH + h_];
                    if (mq == 0 || maskS[kpos]     == 0) v0 = -FLT_MAX;
                    if (mq == 0 || maskS[kpos + 1] == 0) v1 = -FLT_MAX;
                    *reinterpret_cast<float2*>(P + qr * PSTR + kpos) = make_float2(v0, v1);
                }
            }
        }
        __syncthreads();
    }

    // V chunk 0 overlaps softmax
    at_loadKV_cp(Vg, 0, kvOff[0], 72, tid);
    cp_commit();

    // ---- softmax ----
    for (int r = wid; r < 64; r += 8) {
        float m = -FLT_MAX;
        #pragma unroll
        for (int c = 0; c < 16; c++) m = fmaxf(m, P[r * PSTR + lane + c * 32]);
        #pragma unroll
        for (int o = 16; o > 0; o >>= 1) m = fmaxf(m, __shfl_xor_sync(0xffffffffu, m, o));
        float s = 0.f;
        #pragma unroll
        for (int c = 0; c < 16; c++) {
            float e = __expf(P[r * PSTR + lane + c * 32] - m);
            P[r * PSTR + lane + c * 32] = e;
            s += e;
        }
        #pragma unroll
        for (int o = 16; o > 0; o >>= 1) s += __shfl_xor_sync(0xffffffffu, s, o);
        float inv = 1.0f / s;
        #pragma unroll
        for (int c = 0; c < 16; c++) P[r * PSTR + lane + c * 32] *= inv;
    }
    __syncthreads();

    // ---- out = P @ V ----
    {
        const int wmv = wid >> 1, wnv = wid & 1;
        float acc2[4][4] = {};
        const int row0 = wmv * 16 + (lane >> 2);

        for (int kc = 0; kc < 4; kc++) {
            int cur = kc & 1;
            if (kc + 1 < 4) {
                at_loadKV_cp(Vg, kc + 1, kvOff[cur ^ 1], 72, tid);
                cp_commit();
                cp_wait1();
            } else {
                cp_wait0();
            }
            __syncthreads();
            const float* Vs = KV[cur];

            #pragma unroll
            for (int ks = 0; ks < 16; ks++) {
                int ck = kc * 128 + ks * 8 + (lane & 3);
                uint32_t a[4];
                a[0] = cvt_tf32(P[row0 * PSTR + ck]);
                a[1] = cvt_tf32(P[(row0 + 8) * PSTR + ck]);
                a[2] = cvt_tf32(P[row0 * PSTR + ck + 4]);
                a[3] = cvt_tf32(P[(row0 + 8) * PSTR + ck + 4]);
                uint32_t bf[2][4];
                #pragma unroll
                for (int j = 0; j < 2; j++) {
                    int d0 = wnv * 32 + j * 16 + (lane >> 2);
                    int kk = ks * 8 + (lane & 3);
                    bf[j][0] = cvt_tf32(Vs[kk * 72 + d0]);
                    bf[j][1] = cvt_tf32(Vs[(kk + 4) * 72 + d0]);
                    bf[j][2] = cvt_tf32(Vs[kk * 72 + d0 + 8]);
                    bf[j][3] = cvt_tf32(Vs[(kk + 4) * 72 + d0 + 8]);
                }
                #pragma unroll
                for (int j = 0; j < 2; j++) {
                    mma8(acc2[2*j],   a, bf[j][0], bf[j][1]);
                    mma8(acc2[2*j+1], a, bf[j][2], bf[j][3]);
                }
            }
            __syncthreads();
        }

        #pragma unroll
        for (int jj = 0; jj < 4; jj++) {
            int d_ = wnv * 32 + jj * 8 + (lane & 3) * 2;
            int q_ = q0 + wmv * 16 + (lane >> 2);
            *reinterpret_cast<float2*>(g_AO + ((size_t)b_ * SS + q_) * EE + h_ * DD + d_) =
                make_float2(acc2[jj][0], acc2[jj][1]);
            *reinterpret_cast<float2*>(g_AO + ((size_t)b_ * SS + q_ + 8) * EE + h_ * DD + d_) =
                make_float2(acc2[jj][2], acc2[jj][3]);
        }
    }
}

// ---------------------------------------------------------------------------
// Launch
// ---------------------------------------------------------------------------
extern "C" void kernel_launch(void* const* d_in, const int* in_sizes, int n_in,
                              void* d_out, int out_size) {
    const float* x       = (const float*)d_in[0];
    const int*   mask    = (const int*)  d_in[1];
    const float* Wq      = (const float*)d_in[2];
    const float* Wk      = (const float*)d_in[3];
    const float* Wv      = (const float*)d_in[4];
    const float* rel_pos = (const float*)d_in[5];
    const float* Wo      = (const float*)d_in[6];
    const float* bo      = (const float*)d_in[7];
    float* out = (float*)d_out;

    const int gemm_smem = G_SMEM_FLOATS * sizeof(float);   // 71,680 B
    const int attn_smem = AT_FLOATS * sizeof(float);       // 207,872 B

    cudaFuncSetAttribute(qkv_mma_kernel, cudaFuncAttributeMaxDynamicSharedMemorySize, gemm_smem);
    cudaFuncSetAttribute(out_mma_kernel, cudaFuncAttributeMaxDynamicSharedMemorySize, gemm_smem);
    cudaFuncSetAttribute(attn_mma_kernel, cudaFuncAttributeMaxDynamicSharedMemorySize, attn_smem);

    qkv_mma_kernel<<<dim3(EE/128, (BB*SS)/128, 3), 128, gemm_smem>>>(x, Wq, Wk, Wv);
    attn_mma_kernel<<<dim3(8, BB*HH), 256, attn_smem>>>(rel_pos, mask);
    out_mma_kernel<<<dim3(EE/128, (BB*SS)/128), 128, gemm_smem>>>(Wo, bo, out);
}

// round 5
// speedup vs baseline: 3.4523x; 1.0956x over previous
#include <cuda_runtime.h>
#include <math.h>
#include <float.h>
#include <stdint.h>

#define BB 8
#define SS 512
#define EE 768
#define HH 12
#define DD 64
#define ML 512
#define PSTR 516

// Scratch (no cudaMalloc allowed)
__device__ float g_Q[BB*HH*SS*DD];
__device__ float g_K[BB*HH*SS*DD];
__device__ float g_V[BB*HH*SS*DD];
__device__ float g_AO[BB*SS*EE];
__device__ float g_xr[BB*SS*EE];       // tf32-rounded x
__device__ float g_Wr[4*EE*EE];        // tf32-rounded Wq,Wk,Wv,Wo

// ---------------------------------------------------------------------------
// Helpers
// ---------------------------------------------------------------------------
__device__ __forceinline__ uint32_t smem_u32(const void* p) {
    uint32_t a;
    asm("{ .reg .u64 t; cvta.to.shared.u64 t, %1; cvt.u32.u64 %0, t; }"
        : "=r"(a) : "l"(p));
    return a;
}
__device__ __forceinline__ uint32_t cvt_tf32(float x) {
    uint32_t u;
    asm("cvt.rna.tf32.f32 %0, %1;" : "=r"(u) : "f"(x));
    return u;
}
__device__ __forceinline__ float tf32r(float x) { return __uint_as_float(cvt_tf32(x)); }

__device__ __forceinline__ void mma8(float c[4], const uint32_t a[4],
                                     uint32_t b0, uint32_t b1) {
    asm volatile(
        "mma.sync.aligned.m16n8k8.row.col.f32.tf32.tf32.f32 "
        "{%0,%1,%2,%3},{%4,%5,%6,%7},{%8,%9},{%0,%1,%2,%3};"
        : "+f"(c[0]), "+f"(c[1]), "+f"(c[2]), "+f"(c[3])
        : "r"(a[0]), "r"(a[1]), "r"(a[2]), "r"(a[3]), "r"(b0), "r"(b1));
}
__device__ __forceinline__ void cp16(uint32_t dst, const void* src) {
    asm volatile("cp.async.ca.shared.global [%0], [%1], 16;"
                 :: "r"(dst), "l"(src) : "memory");
}
__device__ __forceinline__ void cp_commit() { asm volatile("cp.async.commit_group;" ::: "memory"); }
__device__ __forceinline__ void cp_wait1()  { asm volatile("cp.async.wait_group 1;" ::: "memory"); }
__device__ __forceinline__ void cp_wait0()  { asm volatile("cp.async.wait_group 0;" ::: "memory"); }

// ---------------------------------------------------------------------------
// Kernel 0: pre-round x and W matrices to tf32 (one pass, bandwidth-bound)
// ---------------------------------------------------------------------------
#define NX4 (BB*SS*EE/4)        // 786432
#define NW4 (EE*EE/4)           // 147456
__global__ void __launch_bounds__(256)
round_kernel(const float4* __restrict__ x, const float4* __restrict__ Wq,
             const float4* __restrict__ Wk, const float4* __restrict__ Wv,
             const float4* __restrict__ Wo) {
    int i = blockIdx.x * 256 + threadIdx.x;
    const float4* s;
    float4* d;
    int off;
    if (i < NX4) {
        s = x; d = reinterpret_cast<float4*>(g_xr); off = i;
    } else {
        int j = i - NX4;
        int w = j / NW4;
        off = j - w * NW4;
        s = (w == 0) ? Wq : (w == 1) ? Wk : (w == 2) ? Wv : Wo;
        d = reinterpret_cast<float4*>(g_Wr) + (size_t)w * NW4;
    }
    float4 v = s[off];
    v.x = tf32r(v.x); v.y = tf32r(v.y); v.z = tf32r(v.z); v.w = tf32r(v.w);
    d[off] = v;
}

// ---------------------------------------------------------------------------
// Dense GEMM: C[128,128] tile, 128 threads (2x2 warps), operands pre-rounded.
//   A: [128 rows][stride 36]   B: [32 k-rows][stride 136]
// ---------------------------------------------------------------------------
#define G_SMEM_FLOATS 17920

__device__ __forceinline__ void g_loadA_cp(const float* __restrict__ A, int rowBase,
                                           int k0, uint32_t dstb, int tid) {
    #pragma unroll
    for (int p = 0; p < 8; p++) {
        int t = tid + p * 128;
        int r = t >> 3, seg = t & 7;
        cp16(dstb + (uint32_t)(r * 36 + seg * 4) * 4u,
             A + (size_t)(rowBase + r) * EE + k0 + seg * 4);
    }
}
__device__ __forceinline__ void g_loadB_cp(const float* __restrict__ W, int colBase,
                                           int k0, uint32_t dstb, int tid) {
    #pragma unroll
    for (int p = 0; p < 8; p++) {
        int t = tid + p * 128;
        int k = t >> 5, seg = t & 31;
        cp16(dstb + (uint32_t)(k * 136 + seg * 4) * 4u,
             W + (size_t)(k0 + k) * EE + colBase + seg * 4);
    }
}

__device__ __forceinline__ void gemm_mainloop(const float* __restrict__ A,
                                              const float* __restrict__ W,
                                              int rowBase, int colBase,
                                              float* smf, uint32_t smb,
                                              float acc[4][8][4],
                                              int tid, int lane, int wm, int wn) {
    const uint32_t aOff[2] = {smb, smb + 4608u * 4u};
    const uint32_t bOff[2] = {smb + 9216u * 4u, smb + 13568u * 4u};

    g_loadA_cp(A, rowBase, 0, aOff[0], tid);
    g_loadB_cp(W, colBase, 0, bOff[0], tid);
    cp_commit();

    for (int c = 0; c < 24; c++) {
        int cur = c & 1;
        if (c + 1 < 24) {
            g_loadA_cp(A, rowBase, (c + 1) * 32, aOff[cur ^ 1], tid);
            g_loadB_cp(W, colBase, (c + 1) * 32, bOff[cur ^ 1], tid);
            cp_commit();
            cp_wait1();
        } else {
            cp_wait0();
        }
        __syncthreads();

        const float* Ab = smf + (cur ? 4608 : 0);
        const float* Bb = smf + 9216 + (cur ? 4352 : 0);

        #pragma unroll
        for (int ks = 0; ks < 4; ks++) {
            uint32_t af[4][4], bf[4][4];
            #pragma unroll
            for (int i = 0; i < 4; i++) {
                int R = wm * 64 + i * 16 + (lane >> 2);
                int c0 = ks * 8 + (lane & 3);
                af[i][0] = __float_as_uint(Ab[R * 36 + c0]);
                af[i][1] = __float_as_uint(Ab[(R + 8) * 36 + c0]);
                af[i][2] = __float_as_uint(Ab[R * 36 + c0 + 4]);
                af[i][3] = __float_as_uint(Ab[(R + 8) * 36 + c0 + 4]);
            }
            #pragma unroll
            for (int j = 0; j < 4; j++) {
                int n0 = wn * 64 + j * 16 + (lane >> 2);
                int kk = ks * 8 + (lane & 3);
                bf[j][0] = __float_as_uint(Bb[kk * 136 + n0]);
                bf[j][1] = __float_as_uint(Bb[(kk + 4) * 136 + n0]);
                bf[j][2] = __float_as_uint(Bb[kk * 136 + n0 + 8]);
                bf[j][3] = __float_as_uint(Bb[(kk + 4) * 136 + n0 + 8]);
            }
            #pragma unroll
            for (int i = 0; i < 4; i++)
                #pragma unroll
                for (int j = 0; j < 4; j++) {
                    mma8(acc[i][2*j],   af[i], bf[j][0], bf[j][1]);
                    mma8(acc[i][2*j+1], af[i], bf[j][2], bf[j][3]);
                }
        }
        __syncthreads();
    }
}

// ---------------------------------------------------------------------------
// Kernel 1: QKV projections.  grid (6,32,3), 128 threads.
// Writes Q (pre-scaled by 1/8) / K / V already tf32-rounded.
// ---------------------------------------------------------------------------
__global__ void __launch_bounds__(128)
qkv_mma_kernel() {
    extern __shared__ float smf[];
    const uint32_t smb = smem_u32(smf);
    const int tid = threadIdx.x, lane = tid & 31, wid = tid >> 5;
    const int wm = wid & 1, wn = wid >> 1;
    const float* W = g_Wr + (size_t)blockIdx.z * (EE * EE);
    float* out = (blockIdx.z == 0) ? g_Q : (blockIdx.z == 1 ? g_K : g_V);
    const float sc = (blockIdx.z == 0) ? 0.125f : 1.0f;
    const int rowBase = blockIdx.y * 128, colBase = blockIdx.x * 128;

    float acc[4][8][4] = {};
    gemm_mainloop(g_xr, W, rowBase, colBase, smf, smb, acc, tid, lane, wm, wn);

    #pragma unroll
    for (int i = 0; i < 4; i++) {
        int r0 = rowBase + (wm * 4 + i) * 16 + (lane >> 2);
        #pragma unroll
        for (int j = 0; j < 4; j++)
            #pragma unroll
            for (int slot = 0; slot < 2; slot++) {
                int jj = 2 * j + slot;
                int col = colBase + (wn * 4 + j) * 16 + slot * 8 + (lane & 3) * 2;
                int h_ = col >> 6, d_ = col & 63;
                {
                    int b_ = r0 >> 9, s_ = r0 & 511;
                    *reinterpret_cast<float2*>(out + (((size_t)b_ * HH + h_) * SS + s_) * DD + d_) =
                        make_float2(tf32r(acc[i][jj][0] * sc), tf32r(acc[i][jj][1] * sc));
                }
                {
                    int r1 = r0 + 8;
                    int b_ = r1 >> 9, s_ = r1 & 511;
                    *reinterpret_cast<float2*>(out + (((size_t)b_ * HH + h_) * SS + s_) * DD + d_) =
                        make_float2(tf32r(acc[i][jj][2] * sc), tf32r(acc[i][jj][3] * sc));
                }
            }
    }
}

// ---------------------------------------------------------------------------
// Kernel 3: output projection + bias.  grid (6,32), 128 threads
// ---------------------------------------------------------------------------
__global__ void __launch_bounds__(128)
out_mma_kernel(const float* __restrict__ bo, float* __restrict__ out) {
    extern __shared__ float smf[];
    const uint32_t smb = smem_u32(smf);
    const int tid = threadIdx.x, lane = tid & 31, wid = tid >> 5;
    const int wm = wid & 1, wn = wid >> 1;
    const int rowBase = blockIdx.y * 128, colBase = blockIdx.x * 128;

    float acc[4][8][4] = {};
    gemm_mainloop(g_AO, g_Wr + (size_t)3 * EE * EE, rowBase, colBase,
                  smf, smb, acc, tid, lane, wm, wn);

    #pragma unroll
    for (int i = 0; i < 4; i++) {
        int r0 = rowBase + (wm * 4 + i) * 16 + (lane >> 2);
        #pragma unroll
        for (int j = 0; j < 4; j++)
            #pragma unroll
            for (int slot = 0; slot < 2; slot++) {
                int jj = 2 * j + slot;
                int col = colBase + (wn * 4 + j) * 16 + slot * 8 + (lane & 3) * 2;
                float b0v = bo[col], b1v = bo[col + 1];
                *reinterpret_cast<float2*>(out + (size_t)r0 * EE + col) =
                    make_float2(acc[i][jj][0] + b0v, acc[i][jj][1] + b1v);
                *reinterpret_cast<float2*>(out + (size_t)(r0 + 8) * EE + col) =
                    make_float2(acc[i][jj][2] + b0v, acc[i][jj][3] + b1v);
            }
    }
}

// ---------------------------------------------------------------------------
// Kernel 2: attention.  grid (8,96), 512 threads (16 warps).
// smem floats: P[64*516]=33024 | KV0 @33024 (9216) | KV1 @42240 (9216)
//              | mask(int) @51456 (512)  => 51968 floats = 207,872 B
// Operands arrive pre-rounded; zero cvt in hot loops.
// ---------------------------------------------------------------------------
#define AT_KV0 33024
#define AT_KV1 42240
#define AT_MASK 51456
#define AT_FLOATS 51968

__device__ __forceinline__ void at_loadKV_cp(const float* __restrict__ src, int kc,
                                             uint32_t dstb, int stride, int tid) {
    #pragma unroll
    for (int p = 0; p < 4; p++) {
        int t = tid + p * 512;
        int kp = t >> 4, seg = t & 15;
        cp16(dstb + (uint32_t)(kp * stride + seg * 4) * 4u,
             src + (size_t)(kc * 128 + kp) * DD + seg * 4);
    }
}

__global__ void __launch_bounds__(512)
attn_mma_kernel(const float* __restrict__ rel_pos, const int* __restrict__ mask) {
    extern __shared__ float smf[];
    const uint32_t smb = smem_u32(smf);
    float* P = smf;
    uint32_t* Pu = reinterpret_cast<uint32_t*>(smf);
    const uint32_t kvOff[2] = {smb + AT_KV0 * 4u, smb + AT_KV1 * 4u};
    float* KV[2] = {smf + AT_KV0, smf + AT_KV1};
    int* maskS = reinterpret_cast<int*>(smf + AT_MASK);

    const int qt = blockIdx.x, bh = blockIdx.y;
    const int b_ = bh / HH, h_ = bh % HH;
    const int q0 = qt * 64;
    const int tid = threadIdx.x, lane = tid & 31, wid = tid >> 5;

    const float* Qg = g_Q + (size_t)bh * SS * DD;
    const float* Kg = g_K + (size_t)bh * SS * DD;
    const float* Vg = g_V + (size_t)bh * SS * DD;

    // issue K chunk 0 early
    at_loadKV_cp(Kg, 0, kvOff[0], 68, tid);
    cp_commit();

    // stage Q into P area ([64][68]) + mask
    #pragma unroll
    for (int p = 0; p < 2; p++) {
        int t = tid + p * 512;
        int r = t >> 4, seg = (t & 15) * 4;
        float4 v = *reinterpret_cast<const float4*>(Qg + (size_t)(q0 + r) * DD + seg);
        *reinterpret_cast<float4*>(P + r * 68 + seg) = v;
    }
    maskS[tid] = mask[b_ * SS + tid];
    __syncthreads();

    // Q fragments to registers (already scaled & rounded)
    const int wmq = wid >> 2, wnq = wid & 3;   // 4x4 warp grid
    uint32_t qf[8][4];
    #pragma unroll
    for (int ks = 0; ks < 8; ks++) {
        int R = wmq * 16 + (lane >> 2);
        int c0 = ks * 8 + (lane & 3);
        qf[ks][0] = __float_as_uint(P[R * 68 + c0]);
        qf[ks][1] = __float_as_uint(P[(R + 8) * 68 + c0]);
        qf[ks][2] = __float_as_uint(P[R * 68 + c0 + 4]);
        qf[ks][3] = __float_as_uint(P[(R + 8) * 68 + c0 + 4]);
    }
    __syncthreads();   // P area now free for the score panel

    // ---- QK^T -> P ----
    for (int kc = 0; kc < 4; kc++) {
        int cur = kc & 1;
        if (kc + 1 < 4) {
            at_loadKV_cp(Kg, kc + 1, kvOff[cur ^ 1], 68, tid);
            cp_commit();
            cp_wait1();
        } else {
            cp_wait0();
        }
        __syncthreads();
        const float* Ks = KV[cur];

        float acc[4][4] = {};
        #pragma unroll
        for (int ks = 0; ks < 8; ks++) {
            uint32_t bf[2][4];
            #pragma unroll
            for (int j = 0; j < 2; j++) {
                int n0 = wnq * 32 + j * 16 + (lane >> 2);
                int kk = ks * 8 + (lane & 3);
                bf[j][0] = __float_as_uint(Ks[n0 * 68 + kk]);
                bf[j][1] = __float_as_uint(Ks[n0 * 68 + kk + 4]);
                bf[j][2] = __float_as_uint(Ks[(n0 + 8) * 68 + kk]);
                bf[j][3] = __float_as_uint(Ks[(n0 + 8) * 68 + kk + 4]);
            }
            #pragma unroll
            for (int j = 0; j < 2; j++) {
                mma8(acc[2*j],   qf[ks], bf[j][0], bf[j][1]);
                mma8(acc[2*j+1], qf[ks], bf[j][2], bf[j][3]);
            }
        }

        {
            int qr0 = wmq * 16 + (lane >> 2);
            #pragma unroll
            for (int jj = 0; jj < 4; jj++) {
                int kpos = kc * 128 + wnq * 32 + (jj >> 1) * 16 + (jj & 1) * 8 + (lane & 3) * 2;
                #pragma unroll
                for (int half = 0; half < 2; half++) {
                    int qr = qr0 + half * 8;
                    int qg = q0 + qr;
                    int mq = maskS[qg];
                    float v0 = acc[jj][half*2];
                    float v1 = acc[jj][half*2+1];
                    int i0 = kpos     - qg + (ML - 1);
                    int i1 = kpos + 1 - qg + (ML - 1);
                    i0 = i0 < 0 ? 0 : (i0 > 2*ML-2 ? 2*ML-2 : i0);
                    i1 = i1 < 0 ? 0 : (i1 > 2*ML-2 ? 2*ML-2 : i1);
                    v0 += rel_pos[i0 * HH + h_];
                    v1 += rel_pos[i1 * HH + h_];
                    if (mq == 0 || maskS[kpos]     == 0) v0 = -FLT_MAX;
                    if (mq == 0 || maskS[kpos + 1] == 0) v1 = -FLT_MAX;
                    *reinterpret_cast<float2*>(P + qr * PSTR + kpos) = make_float2(v0, v1);
                }
            }
        }
        __syncthreads();
    }

    // V chunk 0 overlaps softmax
    at_loadKV_cp(Vg, 0, kvOff[0], 72, tid);
    cp_commit();

    // ---- softmax (stores P rounded to tf32) ----
    for (int r = wid; r < 64; r += 16) {
        float m = -FLT_MAX;
        #pragma unroll
        for (int c = 0; c < 16; c++) m = fmaxf(m, P[r * PSTR + lane + c * 32]);
        #pragma unroll
        for (int o = 16; o > 0; o >>= 1) m = fmaxf(m, __shfl_xor_sync(0xffffffffu, m, o));
        float s = 0.f;
        float ev[16];
        #pragma unroll
        for (int c = 0; c < 16; c++) {
            ev[c] = __expf(P[r * PSTR + lane + c * 32] - m);
            s += ev[c];
        }
        #pragma unroll
        for (int o = 16; o > 0; o >>= 1) s += __shfl_xor_sync(0xffffffffu, s, o);
        float inv = 1.0f / s;
        #pragma unroll
        for (int c = 0; c < 16; c++)
            Pu[r * PSTR + lane + c * 32] = cvt_tf32(ev[c] * inv);
    }
    __syncthreads();

    // ---- out = P @ V ----
    {
        const int wmv = wid >> 2, wnv = wid & 3;   // 4x4 warp grid, 16x16 tiles
        float acc2[2][4] = {};
        const int row0 = wmv * 16 + (lane >> 2);

        for (int kc = 0; kc < 4; kc++) {
            int cur = kc & 1;
            if (kc + 1 < 4) {
                at_loadKV_cp(Vg, kc + 1, kvOff[cur ^ 1], 72, tid);
                cp_commit();
                cp_wait1();
            } else {
                cp_wait0();
            }
            __syncthreads();
            const float* Vs = KV[cur];

            #pragma unroll
            for (int ks = 0; ks < 16; ks++) {
                int ck = kc * 128 + ks * 8 + (lane & 3);
                uint32_t a[4];
                a[0] = Pu[row0 * PSTR + ck];
                a[1] = Pu[(row0 + 8) * PSTR + ck];
                a[2] = Pu[row0 * PSTR + ck + 4];
                a[3] = Pu[(row0 + 8) * PSTR + ck + 4];
                uint32_t bf[4];
                int d0 = wnv * 16 + (lane >> 2);
                int kk = ks * 8 + (lane & 3);
                bf[0] = __float_as_uint(Vs[kk * 72 + d0]);
                bf[1] = __float_as_uint(Vs[(kk + 4) * 72 + d0]);
                bf[2] = __float_as_uint(Vs[kk * 72 + d0 + 8]);
                bf[3] = __float_as_uint(Vs[(kk + 4) * 72 + d0 + 8]);
                mma8(acc2[0], a, bf[0], bf[1]);
                mma8(acc2[1], a, bf[2], bf[3]);
            }
            __syncthreads();
        }

        #pragma unroll
        for (int jj = 0; jj < 2; jj++) {
            int d_ = wnv * 16 + jj * 8 + (lane & 3) * 2;
            int q_ = q0 + wmv * 16 + (lane >> 2);
            *reinterpret_cast<float2*>(g_AO + ((size_t)b_ * SS + q_) * EE + h_ * DD + d_) =
                make_float2(tf32r(acc2[jj][0]), tf32r(acc2[jj][1]));
            *reinterpret_cast<float2*>(g_AO + ((size_t)b_ * SS + q_ + 8) * EE + h_ * DD + d_) =
                make_float2(tf32r(acc2[jj][2]), tf32r(acc2[jj][3]));
        }
    }
}

// ---------------------------------------------------------------------------
// Launch
// ---------------------------------------------------------------------------
extern "C" void kernel_launch(void* const* d_in, const int* in_sizes, int n_in,
                              void* d_out, int out_size) {
    const float* x       = (const float*)d_in[0];
    const int*   mask    = (const int*)  d_in[1];
    const float* Wq      = (const float*)d_in[2];
    const float* Wk      = (const float*)d_in[3];
    const float* Wv      = (const float*)d_in[4];
    const float* rel_pos = (const float*)d_in[5];
    const float* Wo      = (const float*)d_in[6];
    const float* bo      = (const float*)d_in[7];
    float* out = (float*)d_out;

    const int gemm_smem = G_SMEM_FLOATS * sizeof(float);   // 71,680 B
    const int attn_smem = AT_FLOATS * sizeof(float);       // 207,872 B

    cudaFuncSetAttribute(qkv_mma_kernel, cudaFuncAttributeMaxDynamicSharedMemorySize, gemm_smem);
    cudaFuncSetAttribute(out_mma_kernel, cudaFuncAttributeMaxDynamicSharedMemorySize, gemm_smem);
    cudaFuncSetAttribute(attn_mma_kernel, cudaFuncAttributeMaxDynamicSharedMemorySize, attn_smem);

    int nround = (NX4 + 4 * NW4 + 255) / 256;   // 5376 blocks
    round_kernel<<<nround, 256>>>((const float4*)x, (const float4*)Wq,
                                  (const float4*)Wk, (const float4*)Wv,
                                  (const float4*)Wo);
    qkv_mma_kernel<<<dim3(EE/128, (BB*SS)/128, 3), 128, gemm_smem>>>();
    attn_mma_kernel<<<dim3(8, BB*HH), 512, attn_smem>>>(rel_pos, mask);
    out_mma_kernel<<<dim3(EE/128, (BB*SS)/128), 128, gemm_smem>>>(bo, out);
}